// round 4
// baseline (speedup 1.0000x reference)
#include <cuda_runtime.h>
#include <cstdint>
#include <math.h>

#define TOPK 8
#define NSPECIAL 999
#define NT 256
#define DDIM 768

// jax.lax.top_k ordering: higher value first; ties -> lower index first.
__device__ __forceinline__ bool better(float v1, int i1, float v2, int i2) {
    return (v1 > v2) || (v1 == v2 && i1 < i2);
}

__device__ __forceinline__ void ins8(float v, int i, float lv[TOPK], int li[TOPK]) {
    if (!better(v, i, lv[TOPK - 1], li[TOPK - 1])) return;
    lv[TOPK - 1] = v; li[TOPK - 1] = i;
#pragma unroll
    for (int k = TOPK - 1; k > 0; k--) {
        if (better(lv[k], li[k], lv[k - 1], li[k - 1])) {
            float tv = lv[k]; lv[k] = lv[k - 1]; lv[k - 1] = tv;
            int   ti = li[k]; li[k] = li[k - 1]; li[k - 1] = ti;
        } else {
            break;
        }
    }
}

__global__ __launch_bounds__(NT)
void dvat_kernel(const float* __restrict__ dgrad,   // [BS, D]
                 const float* __restrict__ semb,    // [BS, D]
                 const float* __restrict__ emb,     // [V, D]
                 const int*   __restrict__ tok,     // [BS]
                 const float* __restrict__ lm,      // [BS, V]
                 const int*   __restrict__ amask,   // [BS]
                 const float* __restrict__ ru,      // [BS]
                 float*       __restrict__ out,     // [BS]  (float32 output!)
                 int V)
{
    const int pos = blockIdx.x;
    const int tid = threadIdx.x;
    const int st  = tok[pos];

    // swap mask: non-special token AND rand_u > (1 - 0.3)
    const float thr = 1.0f - 0.3f;
    const bool swap = (st >= NSPECIAL) && (ru[pos] > thr);
    if (!swap) {                       // uniform across the block
        if (tid == 0) out[pos] = (float)st;
        return;
    }

    __shared__ __align__(16) float s_dg[DDIM];
    __shared__ __align__(16) float s_sr[DDIM];
    __shared__ float sv[NT * TOPK];
    __shared__ int   si[NT * TOPK];
    __shared__ float cscore[TOPK];
    __shared__ int   cidx[TOPK];

    // ---- stage delta_grad / src_embeds rows into shared ----
    {
        const float4* g4 = (const float4*)(dgrad + (size_t)pos * DDIM);
        const float4* s4 = (const float4*)(semb  + (size_t)pos * DDIM);
        float4* sg = (float4*)s_dg;
        float4* ss = (float4*)s_sr;
        for (int j = tid; j < DDIM / 4; j += NT) { sg[j] = g4[j]; ss[j] = s4[j]; }
    }

    // ---- per-thread streaming top-8 over pred_lm row ----
    float lv[TOPK]; int li[TOPK];
#pragma unroll
    for (int k = 0; k < TOPK; k++) { lv[k] = -INFINITY; li[k] = 0x7fffffff; }

    {
        const float2* row2 = (const float2*)(lm + (size_t)pos * V);
        const int nv2 = V >> 1;
#pragma unroll 4
        for (int j = tid; j < nv2; j += NT) {
            float2 p = __ldg(row2 + j);
            ins8(p.x, 2 * j,     lv, li);
            ins8(p.y, 2 * j + 1, lv, li);
        }
        for (int j = (V & ~1) + tid; j < V; j += NT) {
            ins8(__ldg(lm + (size_t)pos * V + j), j, lv, li);
        }
    }

    // ---- block merge tree of sorted-8 lists ----
#pragma unroll
    for (int k = 0; k < TOPK; k++) { sv[tid * TOPK + k] = lv[k]; si[tid * TOPK + k] = li[k]; }
    __syncthreads();

    for (int str = NT / 2; str >= 1; str >>= 1) {
        if (tid < str) {
            int ia = tid * TOPK;
            int ib = (tid + str) * TOPK;
            float mv[TOPK]; int mi[TOPK];
#pragma unroll
            for (int k = 0; k < TOPK; k++) {
                float avv = sv[ia]; int aii = si[ia];
                float bvv = sv[ib]; int bii = si[ib];
                bool ta = better(avv, aii, bvv, bii);
                mv[k] = ta ? avv : bvv;
                mi[k] = ta ? aii : bii;
                if (ta) ia++; else ib++;
            }
#pragma unroll
            for (int k = 0; k < TOPK; k++) { sv[tid * TOPK + k] = mv[k]; si[tid * TOPK + k] = mi[k]; }
        }
        __syncthreads();
    }
    // top-8 (value desc, index-asc ties) now at sv[0..7]/si[0..7]

    // ---- score each candidate: one warp per candidate ----
    const int am   = amask[pos];           // reference: topk_idx *= attention_mask
    const int wid  = tid >> 5;
    const int lane = tid & 31;

    int v = si[wid] * am;
    float score = -INFINITY;
    if (v >= NSPECIAL && v != st) {
        const float4* ev = (const float4*)(emb + (size_t)v * DDIM);
        const float4* g4 = (const float4*)s_dg;
        const float4* s4 = (const float4*)s_sr;
        float gdot = 0.f, sdot = 0.f, vsq = 0.f, pdot = 0.f, ssq = 0.f;
#pragma unroll
        for (int j = lane; j < DDIM / 4; j += 32) {   // 6 iterations
            float4 e = __ldg(ev + j);
            float4 g = g4[j];
            float4 s = s4[j];
            gdot += e.x * g.x + e.y * g.y + e.z * g.z + e.w * g.w;
            sdot += e.x * s.x + e.y * s.y + e.z * s.z + e.w * s.w;
            vsq  += e.x * e.x + e.y * e.y + e.z * e.z + e.w * e.w;
            pdot += g.x * s.x + g.y * s.y + g.z * s.z + g.w * s.w;
            ssq  += s.x * s.x + s.y * s.y + s.z * s.z + s.w * s.w;
        }
#pragma unroll
        for (int o = 16; o > 0; o >>= 1) {
            gdot += __shfl_down_sync(0xffffffffu, gdot, o);
            sdot += __shfl_down_sync(0xffffffffu, sdot, o);
            vsq  += __shfl_down_sync(0xffffffffu, vsq,  o);
            pdot += __shfl_down_sync(0xffffffffu, pdot, o);
            ssq  += __shfl_down_sync(0xffffffffu, ssq,  o);
        }
        if (lane == 0) {
            float sqn = ssq + vsq - 2.0f * sdot;           // src_sq + vocab_sq - 2*dot
            float dn  = sqrtf(fmaxf(sqn, 0.0f) + 1e-20f);  // sqrt(relu(.) + 1e-20)
            score = (gdot - pdot) / dn;                    // (new_dot - prev_dot)/dir_norm
        }
    }
    if (lane == 0) { cscore[wid] = score; cidx[wid] = v; }
    __syncthreads();

    // ---- final argmax with jnp semantics (all -inf -> index 0) ----
    if (tid == 0) {
        float best = 0.f; int bi = 0; bool found = false;
#pragma unroll
        for (int k = 0; k < TOPK; k++) {
            float sc = cscore[k]; int vi = cidx[k];
            if (sc != -INFINITY) {
                if (!found || sc > best || (sc == best && vi < bi)) {
                    best = sc; bi = vi; found = true;
                }
            }
        }
        out[pos] = (float)(found ? bi : 0);
    }
}

extern "C" void kernel_launch(void* const* d_in, const int* in_sizes, int n_in,
                              void* d_out, int out_size) {
    // ---- size-pattern-driven input identification (robust to metadata order) ----
    int idx_lm = 0, idx_emb = 0;
    long sz_lm = -1, sz_emb = -1;
    for (int i = 0; i < n_in; i++) {
        long s = in_sizes[i];
        if (s > sz_lm) { sz_emb = sz_lm; idx_emb = idx_lm; sz_lm = s; idx_lm = i; }
        else if (s > sz_emb) { sz_emb = s; idx_emb = i; }
    }
    int mids[2], nm = 0, smalls[3], ns = 0;
    long sz_small = 0x7fffffff;
    for (int i = 0; i < n_in; i++)
        if (i != idx_lm && i != idx_emb && (long)in_sizes[i] < sz_small) sz_small = in_sizes[i];
    for (int i = 0; i < n_in; i++) {
        if (i == idx_lm || i == idx_emb) continue;
        if ((long)in_sizes[i] == sz_small) { if (ns < 3) smalls[ns++] = i; }
        else                               { if (nm < 2) mids[nm++] = i; }
    }

    int idx_dg = mids[0], idx_se = mids[1];
    int idx_tok, idx_am, idx_ru;
    if (smalls[0] == 0) {           // alphabetical: attention_mask, rand_u, src_tokens
        idx_am = smalls[0]; idx_ru = smalls[1]; idx_tok = smalls[2];
    } else {                        // dict order: src_tokens, attention_mask, rand_u
        idx_tok = smalls[0]; idx_am = smalls[1]; idx_ru = smalls[2];
    }

    const float* dgrad = (const float*)d_in[idx_dg];
    const float* semb  = (const float*)d_in[idx_se];
    const float* emb   = (const float*)d_in[idx_emb];
    const int*   tok   = (const int*)  d_in[idx_tok];
    const float* lm    = (const float*)d_in[idx_lm];
    const int*   am    = (const int*)  d_in[idx_am];
    const float* ru    = (const float*)d_in[idx_ru];
    float* out = (float*)d_out;      // __output__ is float32 (rel_err==1.0 signature)

    const int BS = in_sizes[idx_tok];        // B*S = 2048
    const int V  = in_sizes[idx_lm] / BS;    // 30522

    dvat_kernel<<<BS, NT>>>(dgrad, semb, emb, tok, lm, am, ru, out, V);
}